// round 1
// baseline (speedup 1.0000x reference)
#include <cuda_runtime.h>

#define NNODES 100000
#define NEDGES 3200000
#define NT 128      // nodes per CTA
#define BLK 256     // threads per CTA

// Scratch (device globals: allocation-free, graph-safe)
__device__ float g_ky[(size_t)NNODES * 64];
__device__ float g_sums[(size_t)NNODES * 64];
__device__ float g_cnt[NNODES];

// -------------------------------------------------------------------------
// Zero the scatter accumulators (must be re-zeroed every call: deterministic)
// -------------------------------------------------------------------------
__global__ void zero_kernel() {
    int i = blockIdx.x * blockDim.x + threadIdx.x;
    if (i < NNODES * 16)
        ((float4*)g_sums)[i] = make_float4(0.f, 0.f, 0.f, 0.f);
    if (i < NNODES)
        g_cnt[i] = 0.f;
}

// -------------------------------------------------------------------------
// Fused per-node kernel:
//   h = relu(ea @ W1 + b1)            (N,3)->(N,64)
//   w = h @ W2 + b2                   (N,1024), never materialized
//   y[n,c,j] = sum_k x[n,c,k] * w[n,c,k,j]   (block matmul, CH=4, 16x16)
// DIVCNT: x input is g_sums, divided by max(cnt,1) on load (scatter-mean)
// DOMIX : epilogue applies out = y @ mixW^T + mixb
//
// CTA: 256 threads, 128 nodes. Per channel c: stage W2[:, c*256:+256] (64KB)
// in SMEM; thread (ng=tid>>4, jg=tid&15) computes, for its 8 nodes, the
// 16 w-values {k=0..15, j=jg}, then contracts with x locally -> exclusive
// ownership of y[n, c*16+jg], no atomics.
// -------------------------------------------------------------------------
template<bool DIVCNT, bool DOMIX>
__global__ void __launch_bounds__(BLK, 1)
fused_kernel(const float* __restrict__ xin, const float* __restrict__ ea,
             const float* __restrict__ W1,  const float* __restrict__ b1,
             const float* __restrict__ W2,  const float* __restrict__ b2,
             const float* __restrict__ cnt, const float* __restrict__ mixW,
             const float* __restrict__ mixb, float* __restrict__ yout)
{
    extern __shared__ float sm[];
    float* hs  = sm;                 // NT*64  (32KB)
    float* xs  = sm + NT * 64;       // NT*64  (32KB)
    float* ys  = sm + 2 * NT * 64;   // NT*64  (32KB)
    float* W2s = sm + 3 * NT * 64;   // 64*256 (64KB)
    float* mWs = W2s + 64 * 256;     // 64*64  (16KB)

    const int tid = threadIdx.x;
    const int nb0 = blockIdx.x * NT;

    // ---- h = relu(ea @ W1 + b1) ----
    for (int i = tid; i < NT * 64; i += BLK) {
        int n = i >> 6, m = i & 63;
        int gn = nb0 + n;
        float h = 0.f;
        if (gn < NNODES) {
            float e0 = ea[gn * 3 + 0], e1 = ea[gn * 3 + 1], e2 = ea[gn * 3 + 2];
            h = fmaxf(fmaf(e2, W1[128 + m],
                      fmaf(e1, W1[64 + m],
                      fmaf(e0, W1[m], b1[m]))), 0.f);
        }
        hs[i] = h;
    }

    // ---- load x tile (optionally scatter-mean normalize) ----
    for (int i = tid; i < NT * 16; i += BLK) {
        int gn = nb0 + (i >> 4);
        float4 v = make_float4(0.f, 0.f, 0.f, 0.f);
        if (gn < NNODES) {
            v = ((const float4*)xin)[gn * 16 + (i & 15)];
            if (DIVCNT) {
                float r = 1.f / fmaxf(cnt[gn], 1.f);
                v.x *= r; v.y *= r; v.z *= r; v.w *= r;
            }
        }
        ((float4*)xs)[i] = v;
    }

    if (DOMIX) {
        for (int i = tid; i < 64 * 16; i += BLK)
            ((float4*)mWs)[i] = ((const float4*)mixW)[i];
    }

    const int ng = tid >> 4;   // node group 0..15 (8 nodes each)
    const int jg = tid & 15;   // j index 0..15
    const int nb = ng * 8;

    for (int c = 0; c < 4; c++) {
        __syncthreads();
        // stage W2 channel slice: W2s[m][t] = W2[m, c*256 + t]
        for (int i = tid; i < 64 * 64; i += BLK) {
            int m = i >> 6, q = i & 63;
            ((float4*)(W2s + (m << 8)))[q] =
                *(const float4*)(W2 + m * 1024 + (c << 8) + (q << 2));
        }
        __syncthreads();

        // GEMM: acc[i][k] = sum_m h[nb+i][m] * W2s[m][k*16+jg]
        float acc[8][16];
        #pragma unroll
        for (int i = 0; i < 8; i++)
            #pragma unroll
            for (int k = 0; k < 16; k++) acc[i][k] = 0.f;

        for (int m = 0; m < 64; m += 4) {
            float4 hv4[8];
            #pragma unroll
            for (int i = 0; i < 8; i++)
                hv4[i] = *(const float4*)&hs[(nb + i) * 64 + m];
            #pragma unroll
            for (int mm = 0; mm < 4; mm++) {
                float wv[16];
                #pragma unroll
                for (int k = 0; k < 16; k++)
                    wv[k] = W2s[(m + mm) * 256 + k * 16 + jg];
                #pragma unroll
                for (int i = 0; i < 8; i++) {
                    float hv = (mm == 0) ? hv4[i].x : (mm == 1) ? hv4[i].y
                             : (mm == 2) ? hv4[i].z : hv4[i].w;
                    #pragma unroll
                    for (int k = 0; k < 16; k++)
                        acc[i][k] = fmaf(hv, wv[k], acc[i][k]);
                }
            }
        }

        // epilogue: y[n, c*16+jg] = sum_k x[n, c*16+k] * (acc + b2)
        float b2v[16];
        #pragma unroll
        for (int k = 0; k < 16; k++)
            b2v[k] = b2[(c << 8) + k * 16 + jg];

        #pragma unroll
        for (int i = 0; i < 8; i++) {
            const float* xr = &xs[(nb + i) * 64 + (c << 4)];
            float s = 0.f;
            #pragma unroll
            for (int k = 0; k < 16; k++)
                s = fmaf(xr[k], acc[i][k] + b2v[k], s);
            ys[(nb + i) * 64 + (c << 4) + jg] = s;
        }
    }
    __syncthreads();

    if (!DOMIX) {
        for (int i = tid; i < NT * 16; i += BLK) {
            int gn = nb0 + (i >> 4);
            if (gn < NNODES)
                ((float4*)yout)[gn * 16 + (i & 15)] = ((const float4*)ys)[i];
        }
    } else {
        // out[n,o] = sum_v ys[n][v] * mixW[o][v] + mixb[o]
        const int nz = tid >> 3;  // 0..31, 4 nodes each
        const int og = tid & 7;   // 0..7,  8 outputs each
        float a2[4][8];
        #pragma unroll
        for (int i = 0; i < 4; i++)
            #pragma unroll
            for (int o = 0; o < 8; o++) a2[i][o] = 0.f;

        for (int v = 0; v < 64; v += 4) {
            float4 xv[4], wv[8];
            #pragma unroll
            for (int i = 0; i < 4; i++)
                xv[i] = *(const float4*)&ys[(nz * 4 + i) * 64 + v];
            #pragma unroll
            for (int o = 0; o < 8; o++)
                wv[o] = *(const float4*)&mWs[(og * 8 + o) * 64 + v];
            #pragma unroll
            for (int i = 0; i < 4; i++)
                #pragma unroll
                for (int o = 0; o < 8; o++) {
                    a2[i][o] = fmaf(xv[i].x, wv[o].x, a2[i][o]);
                    a2[i][o] = fmaf(xv[i].y, wv[o].y, a2[i][o]);
                    a2[i][o] = fmaf(xv[i].z, wv[o].z, a2[i][o]);
                    a2[i][o] = fmaf(xv[i].w, wv[o].w, a2[i][o]);
                }
        }
        #pragma unroll
        for (int i = 0; i < 4; i++) {
            int gn = nb0 + nz * 4 + i;
            if (gn < NNODES) {
                #pragma unroll
                for (int o = 0; o < 8; o++)
                    yout[gn * 64 + og * 8 + o] = a2[i][o] + mixb[og * 8 + o];
            }
        }
    }
}

// -------------------------------------------------------------------------
// Scatter-sum over edges: sums[dst] += ky[src]; cnt[dst] += 1
// 16 threads per edge, one float4 vector-atomic each (sm_90+ float4 red).
// -------------------------------------------------------------------------
__global__ void scatter_kernel(const int* __restrict__ ei) {
    int t = blockIdx.x * blockDim.x + threadIdx.x;
    if (t >= NEDGES * 16) return;
    int e = t >> 4, q = t & 15;
    int dst = ei[e];
    int src = ei[NEDGES + e];
    float4 v = ((const float4*)g_ky)[src * 16 + q];
    atomicAdd(&((float4*)g_sums)[dst * 16 + q], v);
    if (q == 0) atomicAdd(&g_cnt[dst], 1.0f);
}

// -------------------------------------------------------------------------
extern "C" void kernel_launch(void* const* d_in, const int* in_sizes, int n_in,
                              void* d_out, int out_size)
{
    const float* x    = (const float*)d_in[0];
    const float* ea   = (const float*)d_in[1];
    const int*   ei   = (const int*)  d_in[2];
    const float* k1W1 = (const float*)d_in[3];
    const float* k1b1 = (const float*)d_in[4];
    const float* k1W2 = (const float*)d_in[5];
    const float* k1b2 = (const float*)d_in[6];
    const float* k2W1 = (const float*)d_in[7];
    const float* k2b1 = (const float*)d_in[8];
    const float* k2W2 = (const float*)d_in[9];
    const float* k2b2 = (const float*)d_in[10];
    const float* mixW = (const float*)d_in[11];
    const float* mixb = (const float*)d_in[12];
    float* out = (float*)d_out;

    float *ky_p = nullptr, *sums_p = nullptr, *cnt_p = nullptr;
    cudaGetSymbolAddress((void**)&ky_p,   g_ky);
    cudaGetSymbolAddress((void**)&sums_p, g_sums);
    cudaGetSymbolAddress((void**)&cnt_p,  g_cnt);

    size_t smem = (size_t)(3 * NT * 64 + 64 * 256 + 64 * 64) * sizeof(float);
    cudaFuncSetAttribute((const void*)fused_kernel<false, false>,
                         cudaFuncAttributeMaxDynamicSharedMemorySize, (int)smem);
    cudaFuncSetAttribute((const void*)fused_kernel<true, true>,
                         cudaFuncAttributeMaxDynamicSharedMemorySize, (int)smem);

    int grid = (NNODES + NT - 1) / NT;

    // 1) zero scatter accumulators
    zero_kernel<<<(NNODES * 16 + 255) / 256, 256>>>();

    // 2) ky_v = blockmm(x, mlp1(ea))
    fused_kernel<false, false><<<grid, BLK, smem>>>(
        x, ea, k1W1, k1b1, k1W2, k1b2, nullptr, nullptr, nullptr, ky_p);

    // 3) scatter-sum + degree count
    scatter_kernel<<<(NEDGES * 16 + 255) / 256, 256>>>(ei);

    // 4) v = blockmm(sums/cnt, mlp2(ea)); out = v @ mixW^T + mixb
    fused_kernel<true, true><<<grid, BLK, smem>>>(
        sums_p, ea, k2W1, k2b1, k2W2, k2b2, cnt_p, mixW, mixb, out);
}

// round 5
// speedup vs baseline: 1.8021x; 1.8021x over previous
#include <cuda_runtime.h>
#include <cuda_bf16.h>
#include <cstdint>

#define NNODES 100000
#define NEDGES 3200000
#define NT 128            // nodes per CTA
#define THREADS 256

// ------------------------- device scratch (no allocs) -----------------------
__device__ __align__(16) float g_ky[(size_t)NNODES * 64];
__device__ __align__(16) float g_sums[(size_t)NNODES * 64];
__device__ float g_cnt[NNODES];
// pre-split, transposed (t-major), SW128-swizzled W2 tiles:
// [ki][c] -> 256 rows (t) x 64 cols (m) bf16, 128B/row, 32KB per tile
__device__ __align__(16) __nv_bfloat16 g_Bh[2 * 4 * 256 * 64];
__device__ __align__(16) __nv_bfloat16 g_Bl[2 * 4 * 256 * 64];

#define SWZ(o) ((o) ^ (((o) >> 3) & 0x70))

__device__ __forceinline__ uint32_t smem_u32(const void* p) {
    uint32_t a;
    asm("{ .reg .u64 t; cvta.to.shared.u64 t, %1; cvt.u32.u64 %0, t; }"
        : "=r"(a) : "l"(p));
    return a;
}
__device__ __forceinline__ void ldsm_x4(uint32_t* r, uint32_t a) {
    asm volatile("ldmatrix.sync.aligned.m8n8.x4.shared.b16 {%0,%1,%2,%3}, [%4];"
                 : "=r"(r[0]), "=r"(r[1]), "=r"(r[2]), "=r"(r[3]) : "r"(a));
}
__device__ __forceinline__ void ldsm_x2(uint32_t* r, uint32_t a) {
    asm volatile("ldmatrix.sync.aligned.m8n8.x2.shared.b16 {%0,%1}, [%2];"
                 : "=r"(r[0]), "=r"(r[1]) : "r"(a));
}
__device__ __forceinline__ void mma16816(float* d, const uint32_t* a, const uint32_t* b) {
    asm volatile("mma.sync.aligned.m16n8k16.row.col.f32.bf16.bf16.f32 "
                 "{%0,%1,%2,%3}, {%4,%5,%6,%7}, {%8,%9}, {%0,%1,%2,%3};"
                 : "+f"(d[0]), "+f"(d[1]), "+f"(d[2]), "+f"(d[3])
                 : "r"(a[0]), "r"(a[1]), "r"(a[2]), "r"(a[3]),
                   "r"(b[0]), "r"(b[1]));
}

// SMEM layout (bytes)
#define SM_AH    0
#define SM_AL    16384
#define SM_BH    32768
#define SM_BL    65536
#define SM_YS    98304                   // 128 rows x 68 floats (padded) = 34816B
#define YSTRIDE  68
#define SM_MIXW  (SM_YS + 34816)         // 64*64 fp32 = 16KB
#define SM_TOTAL (SM_MIXW + 16384)

// ------------------------- prep: split+transpose+swizzle W2 -----------------
__global__ void __launch_bounds__(256)
prep_kernel(const float* __restrict__ W2a, const float* __restrict__ W2b) {
    int id = blockIdx.x * blockDim.x + threadIdx.x;   // 2*4*256*64 = 131072
    if (id >= 131072) return;
    int ki = id >> 16;
    int r  = id & 65535;
    int c  = r >> 14;
    int t  = (r >> 6) & 255;
    int m  = r & 63;
    const float* W2 = ki ? W2b : W2a;
    float w = W2[m * 1024 + c * 256 + t];
    __nv_bfloat16 hi = __float2bfloat16(w);
    __nv_bfloat16 lo = __float2bfloat16(w - __bfloat162float(hi));
    uint32_t off = SWZ((uint32_t)(t * 128 + m * 2));
    size_t tb = (size_t)(ki * 4 + c) * 32768;
    *(__nv_bfloat16*)((char*)g_Bh + tb + off) = hi;
    *(__nv_bfloat16*)((char*)g_Bl + tb + off) = lo;
}

__global__ void __launch_bounds__(256)
zero_kernel() {
    int i = blockIdx.x * blockDim.x + threadIdx.x;
    if (i < NNODES * 16)
        ((float4*)g_sums)[i] = make_float4(0.f, 0.f, 0.f, 0.f);
    if (i < NNODES)
        g_cnt[i] = 0.f;
}

// ------------------------- fused HMMA pass ----------------------------------
// h = relu(ea@W1+b1) -> bf16 split (Ah, Al); per channel c:
// D(128x256) = Ah@Bh^T + Ah@Bl^T + Al@Bh^T  via mma.sync m16n8k16, fp32 acc.
// Epilogue (in fragments): y[n, c*16+j] = sum_k x[n,c*16+k] * (D[n,k*16+j]+b2)
// with x optionally scaled by 1/max(cnt,1). Optional mix linear at the end.
template<bool DIVCNT, bool DOMIX>
__global__ void __launch_bounds__(THREADS, 1)
mma_fused(const float* __restrict__ xin, const float* __restrict__ ea,
          const float* __restrict__ W1,  const float* __restrict__ b1,
          const float* __restrict__ b2,  const float* __restrict__ cnt,
          const float* __restrict__ mixW, const float* __restrict__ mixb,
          float* __restrict__ yout, int ki)
{
    extern __shared__ char smem[];
    const uint32_t smb = smem_u32(smem);
    float* ys = (float*)(smem + SM_YS);
    const int tid = threadIdx.x;
    const int wid = tid >> 5, lid = tid & 31;
    const int nb0 = blockIdx.x * NT;

    // ---- h MLP + bf16 split into A tiles (thread t: node t>>1, 32 m's) ----
    {
        int n = tid >> 1, gn = nb0 + n, mb = (tid & 1) * 32;
        float e0 = 0.f, e1 = 0.f, e2 = 0.f;
        if (gn < NNODES) { e0 = ea[gn*3]; e1 = ea[gn*3+1]; e2 = ea[gn*3+2]; }
        #pragma unroll 8
        for (int q = 0; q < 32; q++) {
            int m = mb + q;
            float h = 0.f;
            if (gn < NNODES)
                h = fmaxf(fmaf(e2, W1[128+m], fmaf(e1, W1[64+m], fmaf(e0, W1[m], b1[m]))), 0.f);
            __nv_bfloat16 hi = __float2bfloat16(h);
            __nv_bfloat16 lo = __float2bfloat16(h - __bfloat162float(hi));
            uint32_t off = SWZ((uint32_t)(n * 128 + m * 2));
            *(__nv_bfloat16*)(smem + SM_AH + off) = hi;
            *(__nv_bfloat16*)(smem + SM_AL + off) = lo;
        }
    }
    if (DOMIX) {
        for (int i = tid; i < 1024; i += THREADS)
            ((float4*)(smem + SM_MIXW))[i] = ((const float4*)mixW)[i];
    }

    const int rb = wid & 3;      // row block (32 rows)
    const int hf = wid >> 2;     // column half
    const uint32_t arow = (uint32_t)(rb * 32 + (lid & 7) + ((lid >> 3) & 1) * 8);
    const uint32_t acol = (uint32_t)(((lid >> 4) & 1) * 8);
    const uint32_t brow = (uint32_t)(lid & 7);
    const uint32_t bcol = (uint32_t)(((lid >> 3) & 1) * 8);
    const int jlo = (lid & 3) * 2;

    // epilogue rows owned by this lane (q = mt*2 + rh)
    int rows[4]; float rcs[4];
    #pragma unroll
    for (int q = 0; q < 4; q++) {
        int mt = q >> 1, rh = q & 1;
        rows[q] = rb * 32 + mt * 16 + rh * 8 + (lid >> 2);
        float r = 1.f;
        int gn = nb0 + rows[q];
        if (DIVCNT && gn < NNODES) r = 1.f / fmaxf(cnt[gn], 1.f);
        rcs[q] = r;
    }

    __syncthreads();   // A tiles staged

    for (int c = 0; c < 4; c++) {
        // stage B tiles (pre-swizzled in global)
        {
            const float4* sh = (const float4*)g_Bh + (size_t)(ki*4 + c) * 2048;
            const float4* sl = (const float4*)g_Bl + (size_t)(ki*4 + c) * 2048;
            float4* dh = (float4*)(smem + SM_BH);
            float4* dl = (float4*)(smem + SM_BL);
            #pragma unroll
            for (int i = 0; i < 8; i++) {
                dh[tid + i*256] = sh[tid + i*256];
                dl[tid + i*256] = sl[tid + i*256];
            }
        }
        __syncthreads();

        float y[16];
        #pragma unroll
        for (int i = 0; i < 16; i++) y[i] = 0.f;

        #pragma unroll
        for (int cb = 0; cb < 2; cb++) {
            float acc[2][8][4];
            #pragma unroll
            for (int mt = 0; mt < 2; mt++)
                #pragma unroll
                for (int nt = 0; nt < 8; nt++)
                    #pragma unroll
                    for (int e = 0; e < 4; e++) acc[mt][nt][e] = 0.f;

            #pragma unroll
            for (int ks = 0; ks < 4; ks++) {
                uint32_t ah[2][4], al[2][4];
                #pragma unroll
                for (int mt = 0; mt < 2; mt++) {
                    uint32_t off = (arow + mt*16) * 128u + (ks*16 + acol) * 2u;
                    ldsm_x4(ah[mt], smb + SM_AH + SWZ(off));
                    ldsm_x4(al[mt], smb + SM_AL + SWZ(off));
                }
                #pragma unroll
                for (int nt = 0; nt < 8; nt++) {
                    uint32_t n0 = (uint32_t)(hf*128 + cb*64 + nt*8);
                    uint32_t off = (n0 + brow) * 128u + (ks*16 + bcol) * 2u;
                    uint32_t bh[2], bl[2];
                    ldsm_x2(bh, smb + SM_BH + SWZ(off));
                    ldsm_x2(bl, smb + SM_BL + SWZ(off));
                    #pragma unroll
                    for (int mt = 0; mt < 2; mt++) {
                        mma16816(acc[mt][nt], ah[mt], bh);
                        mma16816(acc[mt][nt], ah[mt], bl);
                        mma16816(acc[mt][nt], al[mt], bh);
                    }
                }
            }

            // epilogue for this col-block: contract with x
            const int kb = hf * 8 + cb * 4;
            float b2v[8][2];
            #pragma unroll
            for (int nt = 0; nt < 8; nt++) {
                int t0 = c*256 + hf*128 + cb*64 + nt*8 + jlo;
                b2v[nt][0] = b2[t0];
                b2v[nt][1] = b2[t0 + 1];
            }
            #pragma unroll
            for (int q = 0; q < 4; q++) {
                int mt = q >> 1, rh = q & 1;
                int gn = nb0 + rows[q];
                float xk[4] = {0.f, 0.f, 0.f, 0.f};
                if (gn < NNODES) {
                    float4 xv = *(const float4*)(xin + (size_t)gn*64 + c*16 + kb);
                    xk[0] = xv.x * rcs[q]; xk[1] = xv.y * rcs[q];
                    xk[2] = xv.z * rcs[q]; xk[3] = xv.w * rcs[q];
                }
                #pragma unroll
                for (int nt = 0; nt < 8; nt++) {
                    int p = (nt & 1) * 2;
                    float xs_ = xk[nt >> 1];
                    y[q*4 + p]     = fmaf(xs_, acc[mt][nt][rh*2]     + b2v[nt][0], y[q*4 + p]);
                    y[q*4 + p + 1] = fmaf(xs_, acc[mt][nt][rh*2 + 1] + b2v[nt][1], y[q*4 + p + 1]);
                }
            }
        }

        // combine col-halves into ys
        if (hf == 0) {
            #pragma unroll
            for (int q = 0; q < 4; q++) {
                float* yp = ys + rows[q] * YSTRIDE + c * 16;
                yp[jlo]     = y[q*4];     yp[jlo + 1] = y[q*4 + 1];
                yp[jlo + 8] = y[q*4 + 2]; yp[jlo + 9] = y[q*4 + 3];
            }
        }
        __syncthreads();
        if (hf == 1) {
            #pragma unroll
            for (int q = 0; q < 4; q++) {
                float* yp = ys + rows[q] * YSTRIDE + c * 16;
                yp[jlo]     += y[q*4];     yp[jlo + 1] += y[q*4 + 1];
                yp[jlo + 8] += y[q*4 + 2]; yp[jlo + 9] += y[q*4 + 3];
            }
        }
    }
    __syncthreads();

    // ---- output ----
    if (!DOMIX) {
        for (int i = tid; i < NT * 16; i += THREADS) {
            int n = i >> 4, gn = nb0 + n;
            if (gn < NNODES)
                ((float4*)yout)[(size_t)gn * 16 + (i & 15)] =
                    ((const float4*)ys)[n * (YSTRIDE/4) + (i & 15)];
        }
    } else {
        // out[n,o] = sum_v ys[n][v]*mixW[o][v] + mixb[o]; thread: node tid>>1, 32 o's
        const int n = tid >> 1, ob = (tid & 1) * 32;
        const int gn = nb0 + n;
        const float4* ys4 = (const float4*)(smem + SM_YS) + n * (YSTRIDE/4);
        const float4* mw4 = (const float4*)(smem + SM_MIXW);
        float acc[32];
        #pragma unroll
        for (int o = 0; o < 32; o++) acc[o] = 0.f;
        #pragma unroll 4
        for (int v4 = 0; v4 < 16; v4++) {
            float4 yv = ys4[v4];
            #pragma unroll
            for (int o = 0; o < 32; o++) {
                float4 w4 = mw4[(ob + o) * 16 + v4];
                acc[o] = fmaf(yv.x, w4.x, acc[o]);
                acc[o] = fmaf(yv.y, w4.y, acc[o]);
                acc[o] = fmaf(yv.z, w4.z, acc[o]);
                acc[o] = fmaf(yv.w, w4.w, acc[o]);
            }
        }
        if (gn < NNODES) {
            #pragma unroll
            for (int o = 0; o < 32; o++)
                yout[(size_t)gn * 64 + ob + o] = acc[o] + mixb[ob + o];
        }
    }
}

// ------------------------- scatter-sum over edges ---------------------------
__global__ void __launch_bounds__(256)
scatter_kernel(const int* __restrict__ ei) {
    int t = blockIdx.x * blockDim.x + threadIdx.x;
    if (t >= NEDGES * 16) return;
    int e = t >> 4, q = t & 15;
    int dst = ei[e];
    int src = ei[NEDGES + e];
    float4 v = ((const float4*)g_ky)[(size_t)src * 16 + q];
    atomicAdd(&((float4*)g_sums)[(size_t)dst * 16 + q], v);
    if (q == 0) atomicAdd(&g_cnt[dst], 1.0f);
}

// -----------------------------------------------------------------------------
extern "C" void kernel_launch(void* const* d_in, const int* in_sizes, int n_in,
                              void* d_out, int out_size)
{
    const float* x    = (const float*)d_in[0];
    const float* ea   = (const float*)d_in[1];
    const int*   ei   = (const int*)  d_in[2];
    const float* k1W1 = (const float*)d_in[3];
    const float* k1b1 = (const float*)d_in[4];
    const float* k1W2 = (const float*)d_in[5];
    const float* k1b2 = (const float*)d_in[6];
    const float* k2W1 = (const float*)d_in[7];
    const float* k2b1 = (const float*)d_in[8];
    const float* k2W2 = (const float*)d_in[9];
    const float* k2b2 = (const float*)d_in[10];
    const float* mixW = (const float*)d_in[11];
    const float* mixb = (const float*)d_in[12];
    float* out = (float*)d_out;

    float *ky_p = nullptr, *sums_p = nullptr, *cnt_p = nullptr;
    cudaGetSymbolAddress((void**)&ky_p,   g_ky);
    cudaGetSymbolAddress((void**)&sums_p, g_sums);
    cudaGetSymbolAddress((void**)&cnt_p,  g_cnt);

    cudaFuncSetAttribute((const void*)mma_fused<false, false>,
                         cudaFuncAttributeMaxDynamicSharedMemorySize, SM_TOTAL);
    cudaFuncSetAttribute((const void*)mma_fused<true, true>,
                         cudaFuncAttributeMaxDynamicSharedMemorySize, SM_TOTAL);

    const int grid = (NNODES + NT - 1) / NT;

    prep_kernel<<<512, 256>>>(k1W2, k2W2);
    zero_kernel<<<(NNODES * 16 + 255) / 256, 256>>>();

    mma_fused<false, false><<<grid, THREADS, SM_TOTAL>>>(
        x, ea, k1W1, k1b1, k1b2, nullptr, nullptr, nullptr, ky_p, 0);

    scatter_kernel<<<(NEDGES * 16 + 255) / 256, 256>>>(ei);

    mma_fused<true, true><<<grid, THREADS, SM_TOTAL>>>(
        sums_p, ea, k2W1, k2b1, k2b2, cnt_p, mixW, mixb, out, 1);
}

// round 7
// speedup vs baseline: 2.0108x; 1.1158x over previous
#include <cuda_runtime.h>
#include <cuda_bf16.h>
#include <cstdint>

#define NNODES 100000
#define NEDGES 3200000
#define NT 128            // nodes per CTA
#define THREADS 256

// ------------------------- device scratch (no allocs) -----------------------
__device__ __align__(16) float g_ky[(size_t)NNODES * 64];
__device__ __align__(16) float g_sums[(size_t)NNODES * 64];
__device__ float g_cnt[NNODES];
// pre-split, transposed (t-major), SW128-swizzled W2 tiles:
// [ki][c] -> 256 rows (t) x 64 cols (m) bf16, 128B/row, 32KB per tile
__device__ __align__(16) __nv_bfloat16 g_Bh[2 * 4 * 256 * 64];
__device__ __align__(16) __nv_bfloat16 g_Bl[2 * 4 * 256 * 64];

#define SWZ(o) ((o) ^ (((o) >> 3) & 0x70))

__device__ __forceinline__ uint32_t smem_u32(const void* p) {
    uint32_t a;
    asm("{ .reg .u64 t; cvta.to.shared.u64 t, %1; cvt.u32.u64 %0, t; }"
        : "=r"(a) : "l"(p));
    return a;
}
__device__ __forceinline__ void ldsm_x4(uint32_t* r, uint32_t a) {
    asm volatile("ldmatrix.sync.aligned.m8n8.x4.shared.b16 {%0,%1,%2,%3}, [%4];"
                 : "=r"(r[0]), "=r"(r[1]), "=r"(r[2]), "=r"(r[3]) : "r"(a));
}
__device__ __forceinline__ void ldsm_x2(uint32_t* r, uint32_t a) {
    asm volatile("ldmatrix.sync.aligned.m8n8.x2.shared.b16 {%0,%1}, [%2];"
                 : "=r"(r[0]), "=r"(r[1]) : "r"(a));
}
__device__ __forceinline__ void mma16816(float* d, const uint32_t* a, const uint32_t* b) {
    asm volatile("mma.sync.aligned.m16n8k16.row.col.f32.bf16.bf16.f32 "
                 "{%0,%1,%2,%3}, {%4,%5,%6,%7}, {%8,%9}, {%0,%1,%2,%3};"
                 : "+f"(d[0]), "+f"(d[1]), "+f"(d[2]), "+f"(d[3])
                 : "r"(a[0]), "r"(a[1]), "r"(a[2]), "r"(a[3]),
                   "r"(b[0]), "r"(b[1]));
}
__device__ __forceinline__ void cpasync16(uint32_t dst, const void* src) {
    asm volatile("cp.async.ca.shared.global [%0], [%1], 16;" :: "r"(dst), "l"(src));
}
#define CP_COMMIT() asm volatile("cp.async.commit_group;" ::: "memory")
#define CP_WAIT1()  asm volatile("cp.async.wait_group 1;" ::: "memory")
#define CP_WAIT0()  asm volatile("cp.async.wait_group 0;" ::: "memory")

// SMEM layout (bytes)
#define SM_AH    0
#define SM_AL    16384
#define SM_B0    32768          // buffer 0: Bh @ +0, Bl @ +32768 (64KB)
#define SM_B1    98304          // buffer 1
#define SM_YS    163840         // 128 x 68 floats padded = 34816B
#define YSTRIDE  68
#define SM_MIXW  198656         // 64*64 fp32 = 16KB
#define SM_TOTAL 215040

// ------------------------- prep: split+transpose+swizzle W2 -----------------
__global__ void __launch_bounds__(256)
prep_kernel(const float* __restrict__ W2a, const float* __restrict__ W2b) {
    int id = blockIdx.x * blockDim.x + threadIdx.x;   // 2*4*256*64 = 131072
    if (id >= 131072) return;
    int ki = id >> 16;
    int r  = id & 65535;
    int c  = r >> 14;
    int t  = (r >> 6) & 255;
    int m  = r & 63;
    const float* W2 = ki ? W2b : W2a;
    float w = W2[m * 1024 + c * 256 + t];
    __nv_bfloat16 hi = __float2bfloat16(w);
    __nv_bfloat16 lo = __float2bfloat16(w - __bfloat162float(hi));
    uint32_t off = SWZ((uint32_t)(t * 128 + m * 2));
    size_t tb = (size_t)(ki * 4 + c) * 32768;
    *(__nv_bfloat16*)((char*)g_Bh + tb + off) = hi;
    *(__nv_bfloat16*)((char*)g_Bl + tb + off) = lo;
}

__global__ void __launch_bounds__(256)
zero_kernel() {
    int i = blockIdx.x * blockDim.x + threadIdx.x;
    if (i < NNODES * 16)
        ((float4*)g_sums)[i] = make_float4(0.f, 0.f, 0.f, 0.f);
    if (i < NNODES)
        g_cnt[i] = 0.f;
}

// ------------------------- B tile staging via cp.async ----------------------
__device__ __forceinline__ void stage_B(uint32_t smb, int buf, int ki, int c, int tid) {
    uint32_t dst = smb + SM_B0 + (uint32_t)buf * 65536u;
    const char* sh = (const char*)g_Bh + (size_t)(ki * 4 + c) * 32768;
    const char* sl = (const char*)g_Bl + (size_t)(ki * 4 + c) * 32768;
    #pragma unroll
    for (int i = 0; i < 8; i++) {
        uint32_t o = (uint32_t)(tid * 16 + i * 4096);
        cpasync16(dst + o, sh + o);
        cpasync16(dst + 32768u + o, sl + o);
    }
}

// ------------------------- fused HMMA pass ----------------------------------
// Warp w: rows (w&3)*32..+32 (2 m-tiles), n-tile parity par=w>>2 -> owns
// all 16 k for j in [8*par, 8*par+8): epilogue fully warp-local.
// Per channel c: D = Ah@Bh^T + Ah@Bl^T + Al@Bh^T (mma.sync, fp32 acc);
// y[n, c*16+j] = sum_k x[n,c*16+k]*(D[n,16k+j]+b2), x scaled by 1/max(cnt,1)
// if DIVCNT. Pass1 stores y directly to global; pass2 stages ys + mix linear.
template<bool DIVCNT, bool DOMIX>
__global__ void __launch_bounds__(THREADS, 1)
mma_fused(const float* __restrict__ xin, const float* __restrict__ ea,
          const float* __restrict__ W1,  const float* __restrict__ b1,
          const float* __restrict__ b2,  const float* __restrict__ cnt,
          const float* __restrict__ mixW, const float* __restrict__ mixb,
          float* __restrict__ yout, int ki)
{
    extern __shared__ char smem[];
    const uint32_t smb = smem_u32(smem);
    float* ys = (float*)(smem + SM_YS);
    const int tid = threadIdx.x;
    const int wid = tid >> 5, lid = tid & 31;
    const int nb0 = blockIdx.x * NT;

    // kick off B staging for channels 0 and 1 immediately
    stage_B(smb, 0, ki, 0, tid); CP_COMMIT();
    stage_B(smb, 1, ki, 1, tid); CP_COMMIT();

    // ---- h MLP + bf16 split into A tiles (thread t: node t>>1, 32 m's) ----
    {
        int n = tid >> 1, gn = nb0 + n, mb = (tid & 1) * 32;
        float e0 = 0.f, e1 = 0.f, e2 = 0.f;
        if (gn < NNODES) { e0 = ea[gn*3]; e1 = ea[gn*3+1]; e2 = ea[gn*3+2]; }
        #pragma unroll 8
        for (int q = 0; q < 32; q++) {
            int m = mb + q;
            float h = 0.f;
            if (gn < NNODES)
                h = fmaxf(fmaf(e2, W1[128+m], fmaf(e1, W1[64+m], fmaf(e0, W1[m], b1[m]))), 0.f);
            __nv_bfloat16 hi = __float2bfloat16(h);
            __nv_bfloat16 lo = __float2bfloat16(h - __bfloat162float(hi));
            uint32_t off = SWZ((uint32_t)(n * 128 + m * 2));
            *(__nv_bfloat16*)(smem + SM_AH + off) = hi;
            *(__nv_bfloat16*)(smem + SM_AL + off) = lo;
        }
    }
    if (DOMIX) {
        for (int i = tid; i < 1024; i += THREADS)
            ((float4*)(smem + SM_MIXW))[i] = ((const float4*)mixW)[i];
    }

    const int rb  = wid & 3;     // row block (32 rows, 2 m-tiles)
    const int par = wid >> 2;    // n-tile parity -> j half
    const uint32_t arow = (uint32_t)(rb * 32 + (lid & 7) + ((lid >> 3) & 1) * 8);
    const uint32_t acol = (uint32_t)(((lid >> 4) & 1) * 8);
    const uint32_t brow = (uint32_t)(lid & 7);
    const uint32_t bcol = (uint32_t)(((lid >> 3) & 1) * 8);
    const int jlo = (lid & 3) * 2;

    // rows owned by this lane: g = mt*2 + rh
    int rowg[4]; float rcs[4];
    #pragma unroll
    for (int g = 0; g < 4; g++) {
        rowg[g] = rb * 32 + (g >> 1) * 16 + (g & 1) * 8 + (lid >> 2);
        float r = 1.f;
        int gn = nb0 + rowg[g];
        if (DIVCNT && gn < NNODES) r = 1.f / fmaxf(cnt[gn], 1.f);
        rcs[g] = r;
    }

    for (int c = 0; c < 4; c++) {
        if (c < 3) CP_WAIT1(); else CP_WAIT0();
        __syncthreads();   // B[c] staged (and A tiles on first iter)
        const uint32_t bufb = smb + SM_B0 + (uint32_t)(c & 1) * 65536u;

        float y[4][2];
        #pragma unroll
        for (int g = 0; g < 4; g++) { y[g][0] = 0.f; y[g][1] = 0.f; }

        #pragma unroll
        for (int qh = 0; qh < 2; qh++) {
            float acc[2][8][4];
            #pragma unroll
            for (int mt = 0; mt < 2; mt++)
                #pragma unroll
                for (int qq = 0; qq < 8; qq++)
                    #pragma unroll
                    for (int e = 0; e < 4; e++) acc[mt][qq][e] = 0.f;

            #pragma unroll
            for (int ks = 0; ks < 4; ks++) {
                uint32_t ah[2][4], al[2][4];
                #pragma unroll
                for (int mt = 0; mt < 2; mt++) {
                    uint32_t off = (arow + mt*16) * 128u + (ks*16 + acol) * 2u;
                    ldsm_x4(ah[mt], smb + SM_AH + SWZ(off));
                    ldsm_x4(al[mt], smb + SM_AL + SWZ(off));
                }
                #pragma unroll
                for (int qq = 0; qq < 8; qq++) {
                    uint32_t n0 = (uint32_t)((qh*8 + qq) * 16 + 8 * par);
                    uint32_t off = (n0 + brow) * 128u + (ks*16 + bcol) * 2u;
                    uint32_t bh[2], bl[2];
                    ldsm_x2(bh, bufb + SWZ(off));
                    ldsm_x2(bl, bufb + 32768u + SWZ(off));
                    #pragma unroll
                    for (int mt = 0; mt < 2; mt++) {
                        mma16816(acc[mt][qq], ah[mt], bh);
                        mma16816(acc[mt][qq], ah[mt], bl);
                        mma16816(acc[mt][qq], al[mt], bh);
                    }
                }
            }

            // epilogue for this q-half: contract with x
            float b2v[8][2];
            #pragma unroll
            for (int qq = 0; qq < 8; qq++) {
                int t0 = c*256 + (qh*8 + qq)*16 + 8*par + jlo;
                b2v[qq][0] = b2[t0];
                b2v[qq][1] = b2[t0 + 1];
            }
            #pragma unroll
            for (int g = 0; g < 4; g++) {
                int mt = g >> 1, rh = g & 1;
                int gn = nb0 + rowg[g];
                float xk[8];
                #pragma unroll
                for (int q = 0; q < 8; q++) xk[q] = 0.f;
                if (gn < NNODES) {
                    float4 a = *(const float4*)(xin + (size_t)gn*64 + c*16 + qh*8);
                    float4 b = *(const float4*)(xin + (size_t)gn*64 + c*16 + qh*8 + 4);
                    xk[0]=a.x*rcs[g]; xk[1]=a.y*rcs[g]; xk[2]=a.z*rcs[g]; xk[3]=a.w*rcs[g];
                    xk[4]=b.x*rcs[g]; xk[5]=b.y*rcs[g]; xk[6]=b.z*rcs[g]; xk[7]=b.w*rcs[g];
                }
                #pragma unroll
                for (int qq = 0; qq < 8; qq++) {
                    y[g][0] = fmaf(xk[qq], acc[mt][qq][rh*2]     + b2v[qq][0], y[g][0]);
                    y[g][1] = fmaf(xk[qq], acc[mt][qq][rh*2 + 1] + b2v[qq][1], y[g][1]);
                }
            }
        }

        // store channel result (warp-exclusive ownership, no combine)
        if (!DOMIX) {
            #pragma unroll
            for (int g = 0; g < 4; g++) {
                int gn = nb0 + rowg[g];
                if (gn < NNODES)
                    *(float2*)(yout + (size_t)gn*64 + c*16 + 8*par + jlo) =
                        make_float2(y[g][0], y[g][1]);
            }
        } else {
            #pragma unroll
            for (int g = 0; g < 4; g++) {
                float* yp = ys + rowg[g]*YSTRIDE + c*16 + 8*par + jlo;
                yp[0] = y[g][0]; yp[1] = y[g][1];
            }
        }

        __syncthreads();   // all warps done with B[c] buffer
        if (c < 2) { stage_B(smb, c & 1, ki, c + 2, tid); CP_COMMIT(); }
    }

    // ---- mix linear (pass 2 only) ----
    if (DOMIX) {
        // out[n,o] = sum_v ys[n][v]*mixW[o][v] + mixb[o]; thread: node tid>>1, 32 o's
        const int n = tid >> 1, ob = (tid & 1) * 32;
        const int gn = nb0 + n;
        const float4* ys4 = (const float4*)(smem + SM_YS) + n * (YSTRIDE/4);
        const float4* mw4 = (const float4*)(smem + SM_MIXW);
        float acc[32];
        #pragma unroll
        for (int o = 0; o < 32; o++) acc[o] = 0.f;
        #pragma unroll 4
        for (int v4 = 0; v4 < 16; v4++) {
            float4 yv = ys4[v4];
            #pragma unroll
            for (int o = 0; o < 32; o++) {
                float4 w4 = mw4[(ob + o) * 16 + v4];
                acc[o] = fmaf(yv.x, w4.x, acc[o]);
                acc[o] = fmaf(yv.y, w4.y, acc[o]);
                acc[o] = fmaf(yv.z, w4.z, acc[o]);
                acc[o] = fmaf(yv.w, w4.w, acc[o]);
            }
        }
        if (gn < NNODES) {
            #pragma unroll
            for (int o = 0; o < 32; o++)
                yout[(size_t)gn * 64 + ob + o] = acc[o] + mixb[ob + o];
        }
    }
}

// ------------------------- scatter-sum over edges (ILP x4) ------------------
__global__ void __launch_bounds__(256)
scatter_kernel(const int* __restrict__ ei) {
    const int QE = NEDGES / 4;                       // 800000
    int t = blockIdx.x * blockDim.x + threadIdx.x;   // QE*16 = 12.8M threads
    if (t >= QE * 16) return;
    int e0 = t >> 4, q = t & 15;
    int dst[4], src[4];
    #pragma unroll
    for (int i = 0; i < 4; i++) {
        int e = e0 + i * QE;
        dst[i] = ei[e];
        src[i] = ei[NEDGES + e];
    }
    float4 v[4];
    #pragma unroll
    for (int i = 0; i < 4; i++)
        v[i] = ((const float4*)g_ky)[(size_t)src[i] * 16 + q];
    #pragma unroll
    for (int i = 0; i < 4; i++)
        atomicAdd(&((float4*)g_sums)[(size_t)dst[i] * 16 + q], v[i]);
    if (q == 0) {
        #pragma unroll
        for (int i = 0; i < 4; i++)
            atomicAdd(&g_cnt[dst[i]], 1.0f);
    }
}

// -----------------------------------------------------------------------------
extern "C" void kernel_launch(void* const* d_in, const int* in_sizes, int n_in,
                              void* d_out, int out_size)
{
    const float* x    = (const float*)d_in[0];
    const float* ea   = (const float*)d_in[1];
    const int*   ei   = (const int*)  d_in[2];
    const float* k1W1 = (const float*)d_in[3];
    const float* k1b1 = (const float*)d_in[4];
    const float* k1W2 = (const float*)d_in[5];
    const float* k1b2 = (const float*)d_in[6];
    const float* k2W1 = (const float*)d_in[7];
    const float* k2b1 = (const float*)d_in[8];
    const float* k2W2 = (const float*)d_in[9];
    const float* k2b2 = (const float*)d_in[10];
    const float* mixW = (const float*)d_in[11];
    const float* mixb = (const float*)d_in[12];
    float* out = (float*)d_out;

    float *ky_p = nullptr, *sums_p = nullptr, *cnt_p = nullptr;
    cudaGetSymbolAddress((void**)&ky_p,   g_ky);
    cudaGetSymbolAddress((void**)&sums_p, g_sums);
    cudaGetSymbolAddress((void**)&cnt_p,  g_cnt);

    cudaFuncSetAttribute((const void*)mma_fused<false, false>,
                         cudaFuncAttributeMaxDynamicSharedMemorySize, SM_TOTAL);
    cudaFuncSetAttribute((const void*)mma_fused<true, true>,
                         cudaFuncAttributeMaxDynamicSharedMemorySize, SM_TOTAL);

    const int grid = (NNODES + NT - 1) / NT;

    prep_kernel<<<512, 256>>>(k1W2, k2W2);
    zero_kernel<<<(NNODES * 16 + 255) / 256, 256>>>();

    mma_fused<false, false><<<grid, THREADS, SM_TOTAL>>>(
        x, ea, k1W1, k1b1, k1b2, nullptr, nullptr, nullptr, ky_p, 0);

    scatter_kernel<<<(NEDGES / 4 * 16 + 255) / 256, 256>>>(ei);

    mma_fused<true, true><<<grid, THREADS, SM_TOTAL>>>(
        sums_p, ea, k2W1, k2b1, k2b2, cnt_p, mixW, mixb, out, 1);
}